// round 9
// baseline (speedup 1.0000x reference)
#include <cuda_runtime.h>
#include <cuda_bf16.h>
#include <cstdint>
#include <math.h>

#define NPTS   400000
#define KOFF   27
#define TILE_M 128
#define NTILES (NPTS / TILE_M)    // 3125 exact
#define CPAD   64                 // padded channel dim -> 128B bf16 rows
#define NOUT   38
#define NPADB  40                 // MMA N (5 x n8 tiles)

// ---------------- global scratch (static zero-init; no allocation) ----------------
__device__ __nv_bfloat16 g_fhi[(size_t)(NPTS + 1) * CPAD];
__device__ __nv_bfloat16 g_flo[(size_t)(NPTS + 1) * CPAD];
__device__ __nv_bfloat16 g_hhi[(size_t)(NPTS + 1) * CPAD];
__device__ __nv_bfloat16 g_hlo[(size_t)(NPTS + 1) * CPAD];
__device__ __nv_bfloat16 g_w1hi[KOFF * NPADB * CPAD];
__device__ __nv_bfloat16 g_w1lo[KOFF * NPADB * CPAD];
__device__ __nv_bfloat16 g_w2hi[KOFF * NPADB * CPAD];
__device__ __nv_bfloat16 g_w2lo[KOFF * NPADB * CPAD];

// ---------------- helpers ----------------
__device__ __forceinline__ uint32_t smem_u32(const void* p) {
    uint32_t a;
    asm("{ .reg .u64 t; cvta.to.shared.u64 t, %1; cvt.u32.u64 %0, t; }" : "=r"(a) : "l"(p));
    return a;
}
#define SWZ(o) (((uint32_t)(o)) ^ ((((uint32_t)(o)) >> 3) & 0x70))

__device__ __forceinline__ void cp16(uint32_t dst, const void* src) {
    asm volatile("cp.async.cg.shared.global [%0], [%1], 16;" :: "r"(dst), "l"(src) : "memory");
}
__device__ __forceinline__ void cp_commit() {
    asm volatile("cp.async.commit_group;" ::: "memory");
}
__device__ __forceinline__ void cp_wait0() {
    asm volatile("cp.async.wait_group 0;" ::: "memory");
}

__device__ __forceinline__ void ldsm_x4(uint32_t* r, uint32_t addr) {
    asm volatile("ldmatrix.sync.aligned.m8n8.x4.shared.b16 {%0,%1,%2,%3}, [%4];"
                 : "=r"(r[0]), "=r"(r[1]), "=r"(r[2]), "=r"(r[3]) : "r"(addr));
}
__device__ __forceinline__ void ldsm_x2(uint32_t* r, uint32_t addr) {
    asm volatile("ldmatrix.sync.aligned.m8n8.x2.shared.b16 {%0,%1}, [%2];"
                 : "=r"(r[0]), "=r"(r[1]) : "r"(addr));
}
__device__ __forceinline__ void mma_bf16(float* d, const uint32_t* a, uint32_t b0, uint32_t b1) {
    asm volatile("mma.sync.aligned.m16n8k16.row.col.f32.bf16.bf16.f32 "
                 "{%0,%1,%2,%3}, {%4,%5,%6,%7}, {%8,%9}, {%0,%1,%2,%3};"
                 : "+f"(d[0]), "+f"(d[1]), "+f"(d[2]), "+f"(d[3])
                 : "r"(a[0]), "r"(a[1]), "r"(a[2]), "r"(a[3]), "r"(b0), "r"(b1));
}

// ---------------- smem layout (dynamic, 1024B-aligned base) ----------------
// stage s in {0,1}: A_hi at s*32768, A_lo at s*32768+16384
// B combined (hi 40 rows, lo 40 rows => 80 rows x 128B) at 65536
#define ASTAGE   32768u
#define ALO_REL  16384u
#define B_OFF    65536u
#define BLO_REL  5120u
#define SMEM_DYN (76800u)   // 75776 + 1024 alignment slack

// ---------------- prep kernels ----------------
__global__ void prep_w(const float* __restrict__ W1, const float* __restrict__ W2) {
    int idx = blockIdx.x * 256 + threadIdx.x;
    if (idx >= KOFF * NPADB * CPAD) return;
    int j = idx & (CPAD - 1);
    int n = (idx / CPAD) % NPADB;
    int k = idx / (CPAD * NPADB);
    float w1 = (n < NOUT) ? W1[(k * 64 + j) * NOUT + n] : 0.0f;
    float w2 = (n < NOUT && j < NOUT) ? W2[(k * NOUT + j) * NOUT + n] : 0.0f;
    __nv_bfloat16 h1 = __float2bfloat16(w1);
    g_w1hi[idx] = h1;
    g_w1lo[idx] = __float2bfloat16(w1 - __bfloat162float(h1));
    __nv_bfloat16 h2 = __float2bfloat16(w2);
    g_w2hi[idx] = h2;
    g_w2lo[idx] = __float2bfloat16(w2 - __bfloat162float(h2));
}

__global__ void prep_f(const float* __restrict__ feat) {
    size_t idx = (size_t)blockIdx.x * 256 + threadIdx.x;
    if (idx >= (size_t)(NPTS + 1) * CPAD) return;
    size_t i = idx >> 6;
    float x = (i < NPTS) ? feat[idx] : 0.0f;
    __nv_bfloat16 h = __float2bfloat16(x);
    g_fhi[idx] = h;
    g_flo[idx] = __float2bfloat16(x - __bfloat162float(h));
    if (i == NPTS) {  // zero padding row of h
        g_hhi[idx] = __float2bfloat16(0.0f);
        g_hlo[idx] = __float2bfloat16(0.0f);
    }
}

// ---------------- main conv kernel: pipelined gather + fused 3-pass HMMA ----------------
template <int NKS, bool LAYER2>
__global__ void __launch_bounds__(128, 3) conv_mma(const int* __restrict__ nbr,
                                                   float* __restrict__ out) {
    extern __shared__ char smraw[];
    const uint32_t smu = (smem_u32(smraw) + 1023u) & ~1023u;
    char* smb = smraw + (smu - smem_u32(smraw));
    const int t = threadIdx.x;
    const int lane = t & 31;
    const int wid = t >> 5;               // 0..3, warp owns rows [wid*32, wid*32+32)
    const int i0 = blockIdx.x * TILE_M;

    const __nv_bfloat16* __restrict__ shi = LAYER2 ? g_hhi : g_fhi;
    const __nv_bfloat16* __restrict__ slo = LAYER2 ? g_hlo : g_flo;
    const __nv_bfloat16* __restrict__ whi = LAYER2 ? g_w2hi : g_w1hi;
    const __nv_bfloat16* __restrict__ wlo = LAYER2 ? g_w2lo : g_w1lo;

    float acc[2][5][4];
#pragma unroll
    for (int mt = 0; mt < 2; ++mt)
#pragma unroll
        for (int nt = 0; nt < 5; ++nt)
#pragma unroll
            for (int q = 0; q < 4; ++q) acc[mt][nt][q] = 0.0f;

    // per-thread ldmatrix address components
    const int a_r = (lane & 7) + ((lane >> 3) & 1) * 8;
    const int a_half = (lane >> 4) << 4;
    const int b_r = lane & 7;
    const int b_sub = (lane >> 3) & 3;

    // ---- pipeline helpers ----
    // A gather for offset k into stage buffer (16 cp.asyncs/thread)
    auto issue_A = [&](int k, uint32_t abase) {
#pragma unroll
        for (int i = 0; i < 8; ++i) {
            int q = t + 128 * i;       // 0..1023
            int row = q >> 3, c = q & 7;
            int nb = __ldg(nbr + (size_t)k * NPTS + i0 + row);
            size_t src = (size_t)nb * CPAD + c * 8;
            uint32_t off = SWZ(row * 128 + c * 16);
            cp16(abase + off, shi + src);
            cp16(abase + ALO_REL + off, slo + src);
        }
        cp_commit();
    };
    // B prefetch into regs: combined hi(rows 0..39)+lo(rows 40..79), 5 chunks/thread
    uint4 bregs[5];
    auto loadB = [&](int k) {
        const __nv_bfloat16* wkh = whi + k * (NPADB * CPAD);
        const __nv_bfloat16* wkl = wlo + k * (NPADB * CPAD);
#pragma unroll
        for (int i = 0; i < 5; ++i) {
            int q = t + 128 * i;       // 0..639
            bregs[i] = (q < 320) ? *(const uint4*)(wkh + q * 8)
                                 : *(const uint4*)(wkl + (q - 320) * 8);
        }
    };

    // ---- prologue ----
    issue_A(0, smu);
    loadB(0);

    for (int k = 0; k < KOFF; ++k) {
        const uint32_t abase = smu + (uint32_t)(k & 1) * ASTAGE;
        cp_wait0();                       // A(k) landed (this thread's group)
        // stage B(k) from regs (combined swizzled layout)
#pragma unroll
        for (int i = 0; i < 5; ++i) {
            int q = t + 128 * i;
            *(uint4*)(smb + B_OFF + SWZ(q * 16)) = bregs[i];
        }
        __syncthreads();                  // A(k)+B(k) visible; prev compute finished

        if (k + 1 < KOFF) {
            issue_A(k + 1, smu + (uint32_t)((k + 1) & 1) * ASTAGE);
            loadB(k + 1);
        }

        // ---- load ALL A fragments (hi+lo, both m-subtiles) once ----
        uint32_t ahi[2][NKS][4], alo[2][NKS][4];
#pragma unroll
        for (int mt = 0; mt < 2; ++mt) {
            const int arow = wid * 32 + mt * 16 + a_r;
#pragma unroll
            for (int ks = 0; ks < NKS; ++ks) {
                ldsm_x4(ahi[mt][ks], abase + SWZ(arow * 128 + ks * 32 + a_half));
                ldsm_x4(alo[mt][ks], abase + ALO_REL + SWZ(arow * 128 + ks * 32 + a_half));
            }
        }

        // ---- single B sweep: each B frag (hi & lo) loaded once ----
#pragma unroll
        for (int nt = 0; nt < 5; ++nt) {
            const int brow = nt * 8 + b_r;
#pragma unroll
            for (int ks2 = 0; ks2 < NKS / 2; ++ks2) {
                uint32_t bh[4], bl[4];
                ldsm_x4(bh, smu + B_OFF + SWZ(brow * 128 + ks2 * 64 + b_sub * 16));
                ldsm_x4(bl, smu + B_OFF + BLO_REL + SWZ(brow * 128 + ks2 * 64 + b_sub * 16));
                mma_bf16(acc[0][nt], ahi[0][2 * ks2],     bh[0], bh[1]);
                mma_bf16(acc[1][nt], ahi[1][2 * ks2],     bh[0], bh[1]);
                mma_bf16(acc[0][nt], ahi[0][2 * ks2 + 1], bh[2], bh[3]);
                mma_bf16(acc[1][nt], ahi[1][2 * ks2 + 1], bh[2], bh[3]);
                mma_bf16(acc[0][nt], alo[0][2 * ks2],     bh[0], bh[1]);
                mma_bf16(acc[1][nt], alo[1][2 * ks2],     bh[0], bh[1]);
                mma_bf16(acc[0][nt], alo[0][2 * ks2 + 1], bh[2], bh[3]);
                mma_bf16(acc[1][nt], alo[1][2 * ks2 + 1], bh[2], bh[3]);
                mma_bf16(acc[0][nt], ahi[0][2 * ks2],     bl[0], bl[1]);
                mma_bf16(acc[1][nt], ahi[1][2 * ks2],     bl[0], bl[1]);
                mma_bf16(acc[0][nt], ahi[0][2 * ks2 + 1], bl[2], bl[3]);
                mma_bf16(acc[1][nt], ahi[1][2 * ks2 + 1], bl[2], bl[3]);
            }
            if (NKS & 1) {
                uint32_t bh[2], bl[2];
                ldsm_x2(bh, smu + B_OFF + SWZ(brow * 128 + (NKS - 1) * 32 + (b_sub & 1) * 16));
                ldsm_x2(bl, smu + B_OFF + BLO_REL + SWZ(brow * 128 + (NKS - 1) * 32 + (b_sub & 1) * 16));
                mma_bf16(acc[0][nt], ahi[0][NKS - 1], bh[0], bh[1]);
                mma_bf16(acc[1][nt], ahi[1][NKS - 1], bh[0], bh[1]);
                mma_bf16(acc[0][nt], alo[0][NKS - 1], bh[0], bh[1]);
                mma_bf16(acc[1][nt], alo[1][NKS - 1], bh[0], bh[1]);
                mma_bf16(acc[0][nt], ahi[0][NKS - 1], bl[0], bl[1]);
                mma_bf16(acc[1][nt], ahi[1][NKS - 1], bl[0], bl[1]);
            }
        }
        __syncthreads();   // compute(k) done: B smem & A stage may be overwritten
    }

    // ---- epilogue ----
#pragma unroll
    for (int mt = 0; mt < 2; ++mt) {
        const int r1 = i0 + wid * 32 + mt * 16 + (lane >> 2);
#pragma unroll
        for (int half = 0; half < 2; ++half) {
            const int row = r1 + half * 8;
#pragma unroll
            for (int nt = 0; nt < 5; ++nt) {
                const int c = nt * 8 + (lane & 3) * 2;
                float v0 = acc[mt][nt][half * 2 + 0];
                float v1 = acc[mt][nt][half * 2 + 1];
                if (LAYER2) {
                    if (c < NOUT) {
                        float* o = out + (size_t)row * NOUT + c;
                        o[0] = v0;
                        if (c + 1 < NOUT) o[1] = v1;
                    }
                } else {
                    v0 = 0.5f * v0 * (1.0f + erff(v0 * 0.7071067811865475f));
                    v1 = 0.5f * v1 * (1.0f + erff(v1 * 0.7071067811865475f));
                    __nv_bfloat16 h0 = __float2bfloat16(v0), h1 = __float2bfloat16(v1);
                    __nv_bfloat162 hp; hp.x = h0; hp.y = h1;
                    *(__nv_bfloat162*)(g_hhi + (size_t)row * CPAD + c) = hp;
                    __nv_bfloat162 lp;
                    lp.x = __float2bfloat16(v0 - __bfloat162float(h0));
                    lp.y = __float2bfloat16(v1 - __bfloat162float(h1));
                    *(__nv_bfloat162*)(g_hlo + (size_t)row * CPAD + c) = lp;
                }
            }
        }
    }
}

// ---------------- launch ----------------
extern "C" void kernel_launch(void* const* d_in, const int* in_sizes, int n_in,
                              void* d_out, int out_size) {
    const float* feat = (const float*)d_in[0];  // [N, 64] f32
    const int* nbr    = (const int*)d_in[1];    // [27, N] i32
    const float* W1   = (const float*)d_in[2];  // [27, 64, 38] f32
    const float* W2   = (const float*)d_in[3];  // [27, 38, 38] f32
    float* out        = (float*)d_out;          // [N, 38] f32

    cudaFuncSetAttribute(conv_mma<4, false>, cudaFuncAttributeMaxDynamicSharedMemorySize, SMEM_DYN);
    cudaFuncSetAttribute(conv_mma<3, true >, cudaFuncAttributeMaxDynamicSharedMemorySize, SMEM_DYN);

    prep_w<<<(KOFF * NPADB * CPAD + 255) / 256, 256>>>(W1, W2);
    {
        size_t tot = (size_t)(NPTS + 1) * CPAD;
        prep_f<<<(unsigned)((tot + 255) / 256), 256>>>(feat);
    }
    conv_mma<4, false><<<NTILES, 128, SMEM_DYN>>>(nbr, nullptr);  // layer1 -> g_h (hi/lo)
    conv_mma<3, true ><<<NTILES, 128, SMEM_DYN>>>(nbr, out);      // layer2
}

// round 11
// speedup vs baseline: 4.2175x; 4.2175x over previous
#include <cuda_runtime.h>
#include <cuda_bf16.h>
#include <cstdint>
#include <math.h>

#define NPTS   400000
#define KOFF   27
#define TILE_M 128
#define NTILES (NPTS / TILE_M)    // 3125 exact
#define CPAD   64                 // padded channel dim -> 128B bf16 rows
#define NOUT   38
#define NPADB  40                 // MMA N (5 x n8 tiles)

// ---------------- global scratch (static zero-init; no allocation) ----------------
__device__ __nv_bfloat16 g_fhi[(size_t)(NPTS + 1) * CPAD];
__device__ __nv_bfloat16 g_flo[(size_t)(NPTS + 1) * CPAD];
__device__ __nv_bfloat16 g_hhi[(size_t)(NPTS + 1) * CPAD];
__device__ __nv_bfloat16 g_hlo[(size_t)(NPTS + 1) * CPAD];
__device__ __nv_bfloat16 g_w1hi[KOFF * NPADB * CPAD];
__device__ __nv_bfloat16 g_w1lo[KOFF * NPADB * CPAD];
__device__ __nv_bfloat16 g_w2hi[KOFF * NPADB * CPAD];
__device__ __nv_bfloat16 g_w2lo[KOFF * NPADB * CPAD];

// ---------------- helpers ----------------
__device__ __forceinline__ uint32_t smem_u32(const void* p) {
    uint32_t a;
    asm("{ .reg .u64 t; cvta.to.shared.u64 t, %1; cvt.u32.u64 %0, t; }" : "=r"(a) : "l"(p));
    return a;
}
#define SWZ(o) (((uint32_t)(o)) ^ ((((uint32_t)(o)) >> 3) & 0x70))

// L1-caching async copy: preserves cross-k neighbor-row reuse in L1 (R9's .cg killed it)
__device__ __forceinline__ void cp16ca(uint32_t dst, const void* src) {
    asm volatile("cp.async.ca.shared.global [%0], [%1], 16;" :: "r"(dst), "l"(src) : "memory");
}
__device__ __forceinline__ void cp_commit() {
    asm volatile("cp.async.commit_group;" ::: "memory");
}
__device__ __forceinline__ void cp_wait1() {
    asm volatile("cp.async.wait_group 1;" ::: "memory");
}
__device__ __forceinline__ void cp_wait0() {
    asm volatile("cp.async.wait_group 0;" ::: "memory");
}

__device__ __forceinline__ void ldsm_x4(uint32_t* r, uint32_t addr) {
    asm volatile("ldmatrix.sync.aligned.m8n8.x4.shared.b16 {%0,%1,%2,%3}, [%4];"
                 : "=r"(r[0]), "=r"(r[1]), "=r"(r[2]), "=r"(r[3]) : "r"(addr));
}
__device__ __forceinline__ void ldsm_x2(uint32_t* r, uint32_t addr) {
    asm volatile("ldmatrix.sync.aligned.m8n8.x2.shared.b16 {%0,%1}, [%2];"
                 : "=r"(r[0]), "=r"(r[1]) : "r"(addr));
}
__device__ __forceinline__ void mma_bf16(float* d, const uint32_t* a, uint32_t b0, uint32_t b1) {
    asm volatile("mma.sync.aligned.m16n8k16.row.col.f32.bf16.bf16.f32 "
                 "{%0,%1,%2,%3}, {%4,%5,%6,%7}, {%8,%9}, {%0,%1,%2,%3};"
                 : "+f"(d[0]), "+f"(d[1]), "+f"(d[2]), "+f"(d[3])
                 : "r"(a[0]), "r"(a[1]), "r"(a[2]), "r"(a[3]), "r"(b0), "r"(b1));
}

// ---------------- smem layout (dynamic, 1024B-aligned base) ----------------
// stage s in {0,1}: A_hi at s*32768, A_lo at s*32768+16384; B at 65536 (hi 40 + lo 40 rows)
#define ASTAGE   32768u
#define ALO_REL  16384u
#define B_OFF    65536u
#define BLO_REL  5120u
#define SMEM_DYN 76800u   // 75776 + alignment slack; 3 CTAs/SM

// ---------------- prep kernels ----------------
__global__ void prep_w(const float* __restrict__ W1, const float* __restrict__ W2) {
    int idx = blockIdx.x * 256 + threadIdx.x;
    if (idx >= KOFF * NPADB * CPAD) return;
    int j = idx & (CPAD - 1);
    int n = (idx / CPAD) % NPADB;
    int k = idx / (CPAD * NPADB);
    float w1 = (n < NOUT) ? W1[(k * 64 + j) * NOUT + n] : 0.0f;
    float w2 = (n < NOUT && j < NOUT) ? W2[(k * NOUT + j) * NOUT + n] : 0.0f;
    __nv_bfloat16 h1 = __float2bfloat16(w1);
    g_w1hi[idx] = h1;
    g_w1lo[idx] = __float2bfloat16(w1 - __bfloat162float(h1));
    __nv_bfloat16 h2 = __float2bfloat16(w2);
    g_w2hi[idx] = h2;
    g_w2lo[idx] = __float2bfloat16(w2 - __bfloat162float(h2));
}

__global__ void prep_f(const float* __restrict__ feat) {
    size_t idx = (size_t)blockIdx.x * 256 + threadIdx.x;
    if (idx >= (size_t)(NPTS + 1) * CPAD) return;
    size_t i = idx >> 6;
    float x = (i < NPTS) ? feat[idx] : 0.0f;
    __nv_bfloat16 h = __float2bfloat16(x);
    g_fhi[idx] = h;
    g_flo[idx] = __float2bfloat16(x - __bfloat162float(h));
    if (i == NPTS) {  // zero padding row of h
        g_hhi[idx] = __float2bfloat16(0.0f);
        g_hlo[idx] = __float2bfloat16(0.0f);
    }
}

// ---------------- main conv kernel: L1-cached pipelined gather + fused 3-pass HMMA ----------------
template <int NKS, bool LAYER2>
__global__ void __launch_bounds__(128, 3) conv_mma(const int* __restrict__ nbr,
                                                   float* __restrict__ out) {
    extern __shared__ char smraw[];
    const uint32_t smu = (smem_u32(smraw) + 1023u) & ~1023u;
    char* smb = smraw + (smu - smem_u32(smraw));
    const int t = threadIdx.x;
    const int lane = t & 31;
    const int wid = t >> 5;               // 0..3, warp owns rows [wid*32, wid*32+32)
    const int i0 = blockIdx.x * TILE_M;

    const __nv_bfloat16* __restrict__ shi = LAYER2 ? g_hhi : g_fhi;
    const __nv_bfloat16* __restrict__ slo = LAYER2 ? g_hlo : g_flo;
    const __nv_bfloat16* __restrict__ whi = LAYER2 ? g_w2hi : g_w1hi;
    const __nv_bfloat16* __restrict__ wlo = LAYER2 ? g_w2lo : g_w1lo;

    float acc[2][5][4];
#pragma unroll
    for (int mt = 0; mt < 2; ++mt)
#pragma unroll
        for (int nt = 0; nt < 5; ++nt)
#pragma unroll
            for (int q = 0; q < 4; ++q) acc[mt][nt][q] = 0.0f;

    // per-thread ldmatrix address components
    const int a_r = (lane & 7) + ((lane >> 3) & 1) * 8;
    const int a_half = (lane >> 4) << 4;
    const int b_r = lane & 7;
    const int b_sub = (lane >> 3) & 3;

    // A gather for offset k into stage buffer (16 cp.async.ca / thread, one group)
    auto issue_A = [&](int k, uint32_t abase) {
#pragma unroll
        for (int i = 0; i < 8; ++i) {
            int q = t + 128 * i;       // 0..1023
            int row = q >> 3, c = q & 7;
            int nb = __ldg(nbr + (size_t)k * NPTS + i0 + row);
            size_t src = (size_t)nb * CPAD + c * 8;
            uint32_t off = SWZ(row * 128 + c * 16);
            cp16ca(abase + off, shi + src);
            cp16ca(abase + ALO_REL + off, slo + src);
        }
        cp_commit();
    };

    // ---- prologue ----
    issue_A(0, smu);

    for (int k = 0; k < KOFF; ++k) {
        const uint32_t abase = smu + (uint32_t)(k & 1) * ASTAGE;
        // issue A(k+1) into the other stage (safe: its readers finished at k-1's barrier)
        if (k + 1 < KOFF)
            issue_A(k + 1, smu + (uint32_t)((k + 1) & 1) * ASTAGE);

        // stage B(k): direct LDG->STS (weights L1/L2-hot)
        {
            const __nv_bfloat16* wkh = whi + k * (NPADB * CPAD);
            const __nv_bfloat16* wkl = wlo + k * (NPADB * CPAD);
#pragma unroll
            for (int i = 0; i < 3; ++i) {
                int q = t + 128 * i;
                if (q < NPADB * 8) {
                    int row = q >> 3, c = q & 7;
                    uint32_t off = SWZ(row * 128 + c * 16);
                    *(uint4*)(smb + B_OFF + off) = *(const uint4*)(wkh + row * CPAD + c * 8);
                    *(uint4*)(smb + B_OFF + BLO_REL + off) = *(const uint4*)(wkl + row * CPAD + c * 8);
                }
            }
        }

        if (k + 1 < KOFF) cp_wait1();  // A(k) landed; A(k+1) still in flight
        else              cp_wait0();  // last iter: nothing else pending
        __syncthreads();               // A(k)+B(k) visible to all warps

        // ---- load ALL A fragments (hi+lo, both m-subtiles) once ----
        uint32_t ahi[2][NKS][4], alo[2][NKS][4];
#pragma unroll
        for (int mt = 0; mt < 2; ++mt) {
            const int arow = wid * 32 + mt * 16 + a_r;
#pragma unroll
            for (int ks = 0; ks < NKS; ++ks) {
                ldsm_x4(ahi[mt][ks], abase + SWZ(arow * 128 + ks * 32 + a_half));
                ldsm_x4(alo[mt][ks], abase + ALO_REL + SWZ(arow * 128 + ks * 32 + a_half));
            }
        }

        // ---- single B sweep: each B frag (hi & lo) loaded once ----
#pragma unroll
        for (int nt = 0; nt < 5; ++nt) {
            const int brow = nt * 8 + b_r;
#pragma unroll
            for (int ks2 = 0; ks2 < NKS / 2; ++ks2) {
                uint32_t bh[4], bl[4];
                ldsm_x4(bh, smu + B_OFF + SWZ(brow * 128 + ks2 * 64 + b_sub * 16));
                ldsm_x4(bl, smu + B_OFF + BLO_REL + SWZ(brow * 128 + ks2 * 64 + b_sub * 16));
                mma_bf16(acc[0][nt], ahi[0][2 * ks2],     bh[0], bh[1]);
                mma_bf16(acc[1][nt], ahi[1][2 * ks2],     bh[0], bh[1]);
                mma_bf16(acc[0][nt], ahi[0][2 * ks2 + 1], bh[2], bh[3]);
                mma_bf16(acc[1][nt], ahi[1][2 * ks2 + 1], bh[2], bh[3]);
                mma_bf16(acc[0][nt], alo[0][2 * ks2],     bh[0], bh[1]);
                mma_bf16(acc[1][nt], alo[1][2 * ks2],     bh[0], bh[1]);
                mma_bf16(acc[0][nt], alo[0][2 * ks2 + 1], bh[2], bh[3]);
                mma_bf16(acc[1][nt], alo[1][2 * ks2 + 1], bh[2], bh[3]);
                mma_bf16(acc[0][nt], ahi[0][2 * ks2],     bl[0], bl[1]);
                mma_bf16(acc[1][nt], ahi[1][2 * ks2],     bl[0], bl[1]);
                mma_bf16(acc[0][nt], ahi[0][2 * ks2 + 1], bl[2], bl[3]);
                mma_bf16(acc[1][nt], ahi[1][2 * ks2 + 1], bl[2], bl[3]);
            }
            if (NKS & 1) {
                uint32_t bh[2], bl[2];
                ldsm_x2(bh, smu + B_OFF + SWZ(brow * 128 + (NKS - 1) * 32 + (b_sub & 1) * 16));
                ldsm_x2(bl, smu + B_OFF + BLO_REL + SWZ(brow * 128 + (NKS - 1) * 32 + (b_sub & 1) * 16));
                mma_bf16(acc[0][nt], ahi[0][NKS - 1], bh[0], bh[1]);
                mma_bf16(acc[1][nt], ahi[1][NKS - 1], bh[0], bh[1]);
                mma_bf16(acc[0][nt], alo[0][NKS - 1], bh[0], bh[1]);
                mma_bf16(acc[1][nt], alo[1][NKS - 1], bh[0], bh[1]);
                mma_bf16(acc[0][nt], ahi[0][NKS - 1], bl[0], bl[1]);
                mma_bf16(acc[1][nt], ahi[1][NKS - 1], bl[0], bl[1]);
            }
        }
        __syncthreads();   // compute(k) done: B smem (and A stage for k+2) may be overwritten
    }

    // ---- epilogue ----
#pragma unroll
    for (int mt = 0; mt < 2; ++mt) {
        const int r1 = i0 + wid * 32 + mt * 16 + (lane >> 2);
#pragma unroll
        for (int half = 0; half < 2; ++half) {
            const int row = r1 + half * 8;
#pragma unroll
            for (int nt = 0; nt < 5; ++nt) {
                const int c = nt * 8 + (lane & 3) * 2;
                float v0 = acc[mt][nt][half * 2 + 0];
                float v1 = acc[mt][nt][half * 2 + 1];
                if (LAYER2) {
                    if (c < NOUT) {
                        float* o = out + (size_t)row * NOUT + c;
                        o[0] = v0;
                        if (c + 1 < NOUT) o[1] = v1;
                    }
                } else {
                    v0 = 0.5f * v0 * (1.0f + erff(v0 * 0.7071067811865475f));
                    v1 = 0.5f * v1 * (1.0f + erff(v1 * 0.7071067811865475f));
                    __nv_bfloat16 h0 = __float2bfloat16(v0), h1 = __float2bfloat16(v1);
                    __nv_bfloat162 hp; hp.x = h0; hp.y = h1;
                    *(__nv_bfloat162*)(g_hhi + (size_t)row * CPAD + c) = hp;
                    __nv_bfloat162 lp;
                    lp.x = __float2bfloat16(v0 - __bfloat162float(h0));
                    lp.y = __float2bfloat16(v1 - __bfloat162float(h1));
                    *(__nv_bfloat162*)(g_hlo + (size_t)row * CPAD + c) = lp;
                }
            }
        }
    }
}

// ---------------- launch ----------------
extern "C" void kernel_launch(void* const* d_in, const int* in_sizes, int n_in,
                              void* d_out, int out_size) {
    const float* feat = (const float*)d_in[0];  // [N, 64] f32
    const int* nbr    = (const int*)d_in[1];    // [27, N] i32
    const float* W1   = (const float*)d_in[2];  // [27, 64, 38] f32
    const float* W2   = (const float*)d_in[3];  // [27, 38, 38] f32
    float* out        = (float*)d_out;          // [N, 38] f32

    cudaFuncSetAttribute(conv_mma<4, false>, cudaFuncAttributeMaxDynamicSharedMemorySize, SMEM_DYN);
    cudaFuncSetAttribute(conv_mma<3, true >, cudaFuncAttributeMaxDynamicSharedMemorySize, SMEM_DYN);

    prep_w<<<(KOFF * NPADB * CPAD + 255) / 256, 256>>>(W1, W2);
    {
        size_t tot = (size_t)(NPTS + 1) * CPAD;
        prep_f<<<(unsigned)((tot + 255) / 256), 256>>>(feat);
    }
    conv_mma<4, false><<<NTILES, 128, SMEM_DYN>>>(nbr, nullptr);  // layer1 -> g_h (hi/lo)
    conv_mma<3, true ><<<NTILES, 128, SMEM_DYN>>>(nbr, out);      // layer2
}